// round 14
// baseline (speedup 1.0000x reference)
#include <cuda_runtime.h>
#include <cstdint>

#define TB 4096
#define CB 1024
#define HB 64

// scratch: q [row][h]; k [row][perm16(h)]; vt [b][h][tile*64+perm16(key%64)]
__device__ float g_q[4 * TB * HB];
__device__ float g_k[4 * TB * HB];
__device__ float g_vt[4 * TB * HB];
// split-K partials: [b][t(32)][z(4)][128 rows][64 cols] and [..][128 rows]
__device__ float g_pacc[4 * 32 * 4 * 128 * 64];
__device__ float g_pl[4 * 32 * 4 * 128];

// ---------------------------------------------------------------------------
// helpers
// ---------------------------------------------------------------------------
__device__ __forceinline__ uint32_t f2tf(float f) {
    uint32_t u;
    asm("cvt.rna.tf32.f32 %0, %1;" : "=r"(u) : "f"(f));
    return u;
}

__device__ __forceinline__ void mma8(float* c, const uint32_t* a,
                                     uint32_t b0, uint32_t b1) {
    asm volatile(
        "mma.sync.aligned.m16n8k8.row.col.f32.tf32.tf32.f32 "
        "{%0,%1,%2,%3}, {%4,%5,%6,%7}, {%8,%9}, {%0,%1,%2,%3};"
        : "+f"(c[0]), "+f"(c[1]), "+f"(c[2]), "+f"(c[3])
        : "r"(a[0]), "r"(a[1]), "r"(a[2]), "r"(a[3]), "r"(b0), "r"(b1));
}

// k-fragment permutation: u = 4j + t  ->  32*(j>>3) + 8t + (j&7)
// After permuting dim u, the 16 fragment words {u = 8k+t, 8k+4+t : k=0..7}
// for fixed t live at 4 contiguous uint4s: base+8t, +4, +32, +36, each
// holding (kE_b0, kE_b1, kO_b0, kO_b1).
__device__ __forceinline__ int perm16(int u) {
    int t = u & 3, j = u >> 2;
    return ((j >> 3) << 5) | (t << 3) | (j & 7);
}

#define CP_ASYNC16(dst_u32, src_ptr)                                         \
    asm volatile("cp.async.cg.shared.global [%0], [%1], 16;"                 \
                 :: "r"(dst_u32), "l"(src_ptr) : "memory")

// ---------------------------------------------------------------------------
// Kernel 1: fused QKV projection, tf32 mma, cp.async 3-stage pipeline.
// Epilogue writes K permuted and V transposed+permuted (see layouts above).
// ---------------------------------------------------------------------------
#define XS_STR 36
#define WS_STR 200
#define QKV_STG (64 * XS_STR + 32 * WS_STR)   // words per stage (8704)
#define QKV_SMEM (3 * QKV_STG * 4)            // 104448 B

__global__ __launch_bounds__(256, 2) void qkv_kernel(
    const float* __restrict__ x,
    const float* __restrict__ Wk, const float* __restrict__ bk,
    const float* __restrict__ Wq, const float* __restrict__ bq,
    const float* __restrict__ Wv, const float* __restrict__ bv)
{
    extern __shared__ float qsm[];

    const int tid  = threadIdx.x;
    const int lane = tid & 31;
    const int wid  = tid >> 5;
    const int wr   = wid >> 1;        // 0..3
    const int wc   = wid & 1;         // 0..1
    const int g    = lane >> 2;       // 0..7
    const int tig  = lane & 3;        // 0..3
    const long row0 = (long)blockIdx.x * 64;

    const uint32_t smu = (uint32_t)__cvta_generic_to_shared(qsm);

    float acc[12][4];
#pragma unroll
    for (int nt = 0; nt < 12; nt++)
#pragma unroll
        for (int c = 0; c < 4; c++) acc[nt][c] = 0.f;

#define QKV_ISSUE(kc_, s_)                                                   \
    {                                                                        \
        const uint32_t xb_q = smu + (s_) * QKV_STG * 4;                      \
        const uint32_t wb_q = xb_q + 64 * XS_STR * 4;                        \
        _Pragma("unroll")                                                    \
        for (int i_q = 0; i_q < 2; i_q++) {                                  \
            int f_q = tid + 256 * i_q;                                       \
            int r_q = f_q >> 3, c_q = (f_q & 7) * 4;                         \
            CP_ASYNC16(xb_q + (r_q * XS_STR + c_q) * 4,                      \
                       &x[(row0 + r_q) * CB + (kc_) * 32 + c_q]);            \
        }                                                                    \
        _Pragma("unroll")                                                    \
        for (int i_q = 0; i_q < 6; i_q++) {                                  \
            int f_q = tid + 256 * i_q;                                       \
            int m_q = f_q >> 9, kk_q = (f_q >> 4) & 31, c_q = (f_q & 15) * 4;\
            const float* wp_q = (m_q == 0) ? Wk : ((m_q == 1) ? Wq : Wv);    \
            CP_ASYNC16(wb_q + (kk_q * WS_STR + m_q * 64 + c_q) * 4,          \
                       &wp_q[(long)((kc_) * 32 + kk_q) * HB + c_q]);         \
        }                                                                    \
        asm volatile("cp.async.commit_group;" ::: "memory");                 \
    }

    QKV_ISSUE(0, 0);
    QKV_ISSUE(1, 1);

    const int r0 = 16 * wr + g;

    for (int ck = 0; ck < 32; ck++) {
        if (ck < 31)
            asm volatile("cp.async.wait_group 1;" ::: "memory");
        else
            asm volatile("cp.async.wait_group 0;" ::: "memory");
        __syncthreads();   // chunk ck ready; buffer of chunk ck-1 free

        if (ck + 2 < 32) QKV_ISSUE(ck + 2, (ck + 2) % 3);

        const float* xb = qsm + (ck % 3) * QKV_STG;
        const float* wb = xb + 64 * XS_STR;

#pragma unroll
        for (int kk8 = 0; kk8 < 4; kk8++) {
            uint32_t a[4];
            a[0] = f2tf(xb[r0 * XS_STR + 8 * kk8 + tig]);
            a[1] = f2tf(xb[(r0 + 8) * XS_STR + 8 * kk8 + tig]);
            a[2] = f2tf(xb[r0 * XS_STR + 8 * kk8 + tig + 4]);
            a[3] = f2tf(xb[(r0 + 8) * XS_STR + 8 * kk8 + tig + 4]);
            const float* w0 = wb + (8 * kk8 + tig) * WS_STR + 96 * wc;
            const float* w1 = wb + (8 * kk8 + tig + 4) * WS_STR + 96 * wc;
#pragma unroll
            for (int nt = 0; nt < 12; nt++)
                mma8(acc[nt], a, f2tf(w0[8 * nt + g]), f2tf(w1[8 * nt + g]));
        }
    }

    // epilogue: add bias; Q plain, K permuted, V transposed+permuted
#pragma unroll
    for (int nt = 0; nt < 12; nt++) {
        int gcol = 96 * wc + 8 * nt + 2 * tig;
        int m = gcol >> 6, lc = gcol & 63;
        const float* bp = (m == 0) ? bk : ((m == 1) ? bq : bv);
        float b0 = bp[lc], b1 = bp[lc + 1];
        if (m == 1) {
            float* o = g_q + (row0 + r0) * HB + lc;
            *(float2*)o = make_float2(acc[nt][0] + b0, acc[nt][1] + b1);
            *(float2*)(o + 8 * HB) =
                make_float2(acc[nt][2] + b0, acc[nt][3] + b1);
        } else if (m == 0) {
            int p0 = perm16(lc), p1 = perm16(lc + 1);
            float* o = g_k + (row0 + r0) * HB;
            o[p0] = acc[nt][0] + b0;
            o[p1] = acc[nt][1] + b1;
            o[8 * HB + p0] = acc[nt][2] + b0;
            o[8 * HB + p1] = acc[nt][3] + b1;
        } else {
            long row = row0 + r0;
            long bb = row >> 12;
            int key = (int)(row & 4095);
            int q0 = perm16(key & 63);
            int q1 = perm16((key + 8) & 63);
            float* o = g_vt + bb * (TB * HB) + (long)lc * TB + (key & ~63);
            o[q0]      = acc[nt][0] + b0;
            o[TB + q0] = acc[nt][1] + b1;
            o[q1]      = acc[nt][2] + b0;
            o[TB + q1] = acc[nt][3] + b1;
        }
    }
}

// ---------------------------------------------------------------------------
// Kernel 2: causal flash attention, tf32 mma, 128-row Q tiles, full-width
// warps, split-K z=4. All fragment paths vectorized (LDS.128) via the
// perm16 layouts of K (global), V^T (global) and P (smem staging).
// Grid (16, 4, 4); 2 blocks/SM.
// ---------------------------------------------------------------------------
#define KS_STR 68
#define VS_STR 68
#define PS_STR 68
#define KS0_OFF 0
#define KS1_OFF (64 * KS_STR)
#define VS0_OFF (2 * 64 * KS_STR)
#define VS1_OFF (VS0_OFF + 64 * VS_STR)
#define PS_OFF  (VS0_OFF + 2 * 64 * VS_STR)
#define ATTN_SMEM ((PS_OFF + 128 * PS_STR) * 4)   // 104448 B

__global__ __launch_bounds__(256, 2) void attn_kernel()
{
    extern __shared__ uint32_t sm[];
    uint32_t* ps = sm + PS_OFF;   // [128 rows][perm16(key)] tf32, warp-private

    const int tid  = threadIdx.x;
    const int lane = tid & 31;
    const int wid  = tid >> 5;             // 0..7 = row group
    const int g    = lane >> 2;            // 0..7
    const int tig  = lane & 3;             // 0..3

    const int b = blockIdx.y;
    const int p = blockIdx.x;              // 0..15
    const int z = blockIdx.z;              // 0..3
    const long base = (long)b * TB * HB;
    const float QSC = 0.125f * 1.44269504088896f;  // scale * log2(e)

    const int lr0 = 16 * wid + g;          // local row in 0..127
    const int lr1 = lr0 + 8;

    const uint32_t ksu[2] = { (uint32_t)__cvta_generic_to_shared(sm + KS0_OFF),
                              (uint32_t)__cvta_generic_to_shared(sm + KS1_OFF) };
    const uint32_t vsu[2] = { (uint32_t)__cvta_generic_to_shared(sm + VS0_OFF),
                              (uint32_t)__cvta_generic_to_shared(sm + VS1_OFF) };

// K: rows = keys (already perm16 in h); V^T: rows = h, cols = permuted keys.
#define ATTN_ISSUE(jt_, bi_)                                                 \
    {                                                                        \
        const float* kp_a = g_k + base + (long)((jt_) * 64) * HB;            \
        const float* vp_a = g_vt + base + (long)((jt_) * 64);                \
        _Pragma("unroll")                                                    \
        for (int i_a = 0; i_a < 4; i_a++) {                                  \
            int f_a = tid + 256 * i_a;                                       \
            int r_a = f_a >> 4, c_a = (f_a & 15) * 4;                        \
            CP_ASYNC16(ksu[bi_] + (r_a * KS_STR + c_a) * 4,                  \
                       kp_a + r_a * HB + c_a);                               \
            CP_ASYNC16(vsu[bi_] + (r_a * VS_STR + c_a) * 4,                  \
                       vp_a + (long)r_a * TB + c_a);                         \
        }                                                                    \
        asm volatile("cp.async.commit_group;" ::: "memory");                 \
    }

#pragma unroll 1
    for (int half = 0; half < 2; half++) {
        const int t  = half ? (31 - p) : p;   // 128-row Q tile index
        const int n  = 2 * t + 2;             // total 64-key tiles
        const int j0 = (z * n) >> 2;
        const int j1 = (((z + 1) * n) >> 2) - 1;
        const int cnt = j1 - j0 + 1;          // may be 0

        // ---- Q fragments, pre-scaled by scale*log2e ----
        uint32_t aq[8][4];
        {
            const float* qp = g_q + base + (long)t * 128 * HB;
#pragma unroll
            for (int k = 0; k < 8; k++) {
                int c0 = k * 8 + tig;
                aq[k][0] = f2tf(qp[lr0 * HB + c0] * QSC);
                aq[k][1] = f2tf(qp[lr1 * HB + c0] * QSC);
                aq[k][2] = f2tf(qp[lr0 * HB + c0 + 4] * QSC);
                aq[k][3] = f2tf(qp[lr1 * HB + c0 + 4] * QSC);
            }
        }

        float l0 = 0.f, l1 = 0.f;
        float acc[8][4];
#pragma unroll
        for (int nt = 0; nt < 8; nt++)
#pragma unroll
            for (int c = 0; c < 4; c++) acc[nt][c] = 0.f;

        if (cnt >= 1) ATTN_ISSUE(j0, 0);
        if (cnt >= 2) ATTN_ISSUE(j0 + 1, 1);

        for (int jt = j0; jt <= j1; jt++) {
            const int cur = (jt - j0) & 1;
            if (jt < j1)
                asm volatile("cp.async.wait_group 1;" ::: "memory");
            else
                asm volatile("cp.async.wait_group 0;" ::: "memory");
            __syncthreads();   // tile jt visible to all threads

            const uint32_t* ksb = sm + (cur ? KS1_OFF : KS0_OFF);
            const uint32_t* vsb = sm + (cur ? VS1_OFF : VS0_OFF);
            const int koff = 64 * jt - 128 * t;   // for causal mask
            const bool diag = (jt >= 2 * t);

            // ---- S' = (Q*QSC) K^T, two nt-halves; vectorized K frags ----
#pragma unroll 1
            for (int pass = 0; pass < 2; pass++) {
                float sfr[4][4];
#pragma unroll
                for (int nt = 0; nt < 4; nt++)
#pragma unroll
                    for (int c = 0; c < 4; c++) sfr[nt][c] = 0.f;

#pragma unroll
                for (int nt = 0; nt < 4; nt++) {
                    int ntg = pass * 4 + nt;
                    const uint32_t* krow =
                        &ksb[(8 * ntg + g) * KS_STR + 8 * tig];
                    uint4 u0 = *(const uint4*)(krow);
                    uint4 u1 = *(const uint4*)(krow + 4);
                    uint4 u2 = *(const uint4*)(krow + 32);
                    uint4 u3 = *(const uint4*)(krow + 36);
                    mma8(sfr[nt], aq[0], u0.x, u0.y);
                    mma8(sfr[nt], aq[1], u0.z, u0.w);
                    mma8(sfr[nt], aq[2], u1.x, u1.y);
                    mma8(sfr[nt], aq[3], u1.z, u1.w);
                    mma8(sfr[nt], aq[4], u2.x, u2.y);
                    mma8(sfr[nt], aq[5], u2.z, u2.w);
                    mma8(sfr[nt], aq[6], u3.x, u3.y);
                    mma8(sfr[nt], aq[7], u3.z, u3.w);
                }

                if (diag) {
#pragma unroll
                    for (int nt = 0; nt < 4; nt++) {
                        int c0 = 8 * (pass * 4 + nt) + 2 * tig;
#pragma unroll
                        for (int c = 0; c < 4; c++) {
                            int lc = c0 + (c & 1);
                            int lr = (c < 2) ? lr0 : lr1;
                            if (lc + koff > lr) sfr[nt][c] = -1e30f;
                        }
                    }
                }

#pragma unroll
                for (int nt = 0; nt < 4; nt++) {
                    float e0 = exp2f(sfr[nt][0]);
                    float e1 = exp2f(sfr[nt][1]);
                    float e2 = exp2f(sfr[nt][2]);
                    float e3 = exp2f(sfr[nt][3]);
                    l0 += e0 + e1;
                    l1 += e2 + e3;
                    int col = 8 * (pass * 4 + nt) + 2 * tig;
                    int p0 = perm16(col);      // col+1 -> p0 + 8
                    ps[lr0 * PS_STR + p0]     = f2tf(e0);
                    ps[lr0 * PS_STR + p0 + 8] = f2tf(e1);
                    ps[lr1 * PS_STR + p0]     = f2tf(e2);
                    ps[lr1 * PS_STR + p0 + 8] = f2tf(e3);
                }
            }
            __syncwarp();   // P rows are warp-private

            // ---- O += P V : vectorized P (A) and V^T (B) fragments ----
#pragma unroll
            for (int kh = 0; kh < 2; kh++) {
                const uint32_t* pr0 = &ps[lr0 * PS_STR + 32 * kh + 8 * tig];
                const uint32_t* pr1 = &ps[lr1 * PS_STR + 32 * kh + 8 * tig];
                uint4 f0a = *(const uint4*)(pr0);
                uint4 f0b = *(const uint4*)(pr0 + 4);
                uint4 f1a = *(const uint4*)(pr1);
                uint4 f1b = *(const uint4*)(pr1 + 4);
                uint32_t apA[4] = {f0a.x, f1a.x, f0a.y, f1a.y};  // kg=4kh
                uint32_t apB[4] = {f0a.z, f1a.z, f0a.w, f1a.w};  // kg+1
                uint32_t apC[4] = {f0b.x, f1b.x, f0b.y, f1b.y};  // kg+2
                uint32_t apD[4] = {f0b.z, f1b.z, f0b.w, f1b.w};  // kg+3
#pragma unroll
                for (int nt = 0; nt < 8; nt++) {
                    const uint32_t* vrow =
                        &vsb[(8 * nt + g) * VS_STR + 32 * kh + 8 * tig];
                    uint4 va = *(const uint4*)(vrow);
                    uint4 vb = *(const uint4*)(vrow + 4);
                    mma8(acc[nt], apA, va.x, va.y);
                    mma8(acc[nt], apB, va.z, va.w);
                    mma8(acc[nt], apC, vb.x, vb.y);
                    mma8(acc[nt], apD, vb.z, vb.w);
                }
            }

            __syncthreads();   // all warps done with buf[cur]
            if (jt + 2 <= j1) ATTN_ISSUE(jt + 2, cur);
        }

        // ---- in-warp row-sum reduce; write partials ----
        l0 += __shfl_xor_sync(0xffffffffu, l0, 1);
        l0 += __shfl_xor_sync(0xffffffffu, l0, 2);
        l1 += __shfl_xor_sync(0xffffffffu, l1, 1);
        l1 += __shfl_xor_sync(0xffffffffu, l1, 2);

        const long pidx = (long)((b * 32 + t) * 4 + z);
        if (tig == 0) {
            g_pl[pidx * 128 + lr0] = l0;
            g_pl[pidx * 128 + lr1] = l1;
        }
        float* pa = g_pacc + pidx * 128 * 64;
#pragma unroll
        for (int nt = 0; nt < 8; nt++) {
            int col = 8 * nt + 2 * tig;
            *(float2*)&pa[lr0 * 64 + col] = make_float2(acc[nt][0], acc[nt][1]);
            *(float2*)&pa[lr1 * 64 + col] = make_float2(acc[nt][2], acc[nt][3]);
        }
    }
}

// ---------------------------------------------------------------------------
// Kernel 3: combine 4 split-K partials. Grid (32, 4, 2): one block per
// (row tile t, batch, 64-row half). out = (sum_z acc) / (sum_z l).
// ---------------------------------------------------------------------------
__global__ __launch_bounds__(256) void combine_kernel(float* __restrict__ out)
{
    const int t = blockIdx.x, b = blockIdx.y, hf = blockIdx.z;
    const int tid = threadIdx.x;
    const int rbase = hf * 64;
    const long pbase = (long)((b * 32 + t) * 4);

    __shared__ float linv[64];
    if (tid < 64) {
        float s = 0.f;
#pragma unroll
        for (int z = 0; z < 4; z++)
            s += g_pl[(pbase + z) * 128 + rbase + tid];
        linv[tid] = 1.f / s;
    }
    __syncthreads();

    float* op = out + ((long)b * TB + (long)t * 128 + rbase) * HB;
#pragma unroll
    for (int i = 0; i < 4; i++) {
        int f = tid + 256 * i;
        int r = f >> 4, c = (f & 15) * 4;
        float4 a = make_float4(0.f, 0.f, 0.f, 0.f);
#pragma unroll
        for (int z = 0; z < 4; z++) {
            const float* pa = g_pacc + (pbase + z) * 128 * 64;
            float4 v = *(const float4*)&pa[(rbase + r) * 64 + c];
            a.x += v.x; a.y += v.y; a.z += v.z; a.w += v.w;
        }
        float s = linv[r];
        *(float4*)&op[r * HB + c] =
            make_float4(a.x * s, a.y * s, a.z * s, a.w * s);
    }
}

extern "C" void kernel_launch(void* const* d_in, const int* in_sizes, int n_in,
                              void* d_out, int out_size)
{
    const float* x  = (const float*)d_in[0];
    const float* Wk = (const float*)d_in[1];
    const float* bk = (const float*)d_in[2];
    const float* Wq = (const float*)d_in[3];
    const float* bq = (const float*)d_in[4];
    const float* Wv = (const float*)d_in[5];
    const float* bv = (const float*)d_in[6];
    float* out = (float*)d_out;

    (void)in_sizes; (void)n_in; (void)out_size;

    static bool attr_done = false;
    if (!attr_done) {
        cudaFuncSetAttribute(attn_kernel,
                             cudaFuncAttributeMaxDynamicSharedMemorySize,
                             ATTN_SMEM);
        cudaFuncSetAttribute(qkv_kernel,
                             cudaFuncAttributeMaxDynamicSharedMemorySize,
                             QKV_SMEM);
        attr_done = true;
    }

    qkv_kernel<<<256, 256, QKV_SMEM>>>(x, Wk, bk, Wq, bq, Wv, bv);
    attn_kernel<<<dim3(16, 4, 4), 256, ATTN_SMEM>>>();
    combine_kernel<<<dim3(32, 4, 2), 256>>>(out);
}

// round 16
// speedup vs baseline: 1.0131x; 1.0131x over previous
#include <cuda_runtime.h>
#include <cstdint>

#define TB 4096
#define CB 1024
#define HB 64

// scratch for projected K/Q/V: [B*T, H] each = 4 MiB each
__device__ float g_q[4 * TB * HB];
__device__ float g_k[4 * TB * HB];
__device__ float g_v[4 * TB * HB];
// split-K partials: [b][t(32)][z(4)][128 rows][64 cols] and [..][128 rows]
__device__ float g_pacc[4 * 32 * 4 * 128 * 64];
__device__ float g_pl[4 * 32 * 4 * 128];

// ---------------------------------------------------------------------------
// helpers
// ---------------------------------------------------------------------------
__device__ __forceinline__ uint32_t f2tf(float f) {
    uint32_t u;
    asm("cvt.rna.tf32.f32 %0, %1;" : "=r"(u) : "f"(f));
    return u;
}

__device__ __forceinline__ void mma8(float* c, const uint32_t* a,
                                     uint32_t b0, uint32_t b1) {
    asm volatile(
        "mma.sync.aligned.m16n8k8.row.col.f32.tf32.tf32.f32 "
        "{%0,%1,%2,%3}, {%4,%5,%6,%7}, {%8,%9}, {%0,%1,%2,%3};"
        : "+f"(c[0]), "+f"(c[1]), "+f"(c[2]), "+f"(c[3])
        : "r"(a[0]), "r"(a[1]), "r"(a[2]), "r"(a[3]), "r"(b0), "r"(b1));
}

#define CP_ASYNC16(dst_u32, src_ptr)                                         \
    asm volatile("cp.async.cg.shared.global [%0], [%1], 16;"                 \
                 :: "r"(dst_u32), "l"(src_ptr) : "memory")

// ---------------------------------------------------------------------------
// Kernel 1: fused QKV projection, tf32 mma, cp.async 2-stage ping-pong,
// 3 blocks/SM (69.6 KB smem, <=85 regs). 8 warps in 4x2.
// ---------------------------------------------------------------------------
#define XS_STR 36
#define WS_STR 200
#define QKV_STG (64 * XS_STR + 32 * WS_STR)   // words per stage (8704)
#define QKV_SMEM (2 * QKV_STG * 4)            // 69632 B

__global__ __launch_bounds__(256, 3) void qkv_kernel(
    const float* __restrict__ x,
    const float* __restrict__ Wk, const float* __restrict__ bk,
    const float* __restrict__ Wq, const float* __restrict__ bq,
    const float* __restrict__ Wv, const float* __restrict__ bv)
{
    extern __shared__ float qsm[];

    const int tid  = threadIdx.x;
    const int lane = tid & 31;
    const int wid  = tid >> 5;
    const int wr   = wid >> 1;        // 0..3
    const int wc   = wid & 1;         // 0..1
    const int g    = lane >> 2;       // 0..7
    const int tig  = lane & 3;        // 0..3
    const long row0 = (long)blockIdx.x * 64;

    const uint32_t smu = (uint32_t)__cvta_generic_to_shared(qsm);

    float acc[12][4];
#pragma unroll
    for (int nt = 0; nt < 12; nt++)
#pragma unroll
        for (int c = 0; c < 4; c++) acc[nt][c] = 0.f;

#define QKV_ISSUE(kc_, s_)                                                   \
    {                                                                        \
        const uint32_t xb_q = smu + (s_) * QKV_STG * 4;                      \
        const uint32_t wb_q = xb_q + 64 * XS_STR * 4;                        \
        _Pragma("unroll")                                                    \
        for (int i_q = 0; i_q < 2; i_q++) {                                  \
            int f_q = tid + 256 * i_q;                                       \
            int r_q = f_q >> 3, c_q = (f_q & 7) * 4;                         \
            CP_ASYNC16(xb_q + (r_q * XS_STR + c_q) * 4,                      \
                       &x[(row0 + r_q) * CB + (kc_) * 32 + c_q]);            \
        }                                                                    \
        _Pragma("unroll")                                                    \
        for (int i_q = 0; i_q < 6; i_q++) {                                  \
            int f_q = tid + 256 * i_q;                                       \
            int m_q = f_q >> 9, kk_q = (f_q >> 4) & 31, c_q = (f_q & 15) * 4;\
            const float* wp_q = (m_q == 0) ? Wk : ((m_q == 1) ? Wq : Wv);    \
            CP_ASYNC16(wb_q + (kk_q * WS_STR + m_q * 64 + c_q) * 4,          \
                       &wp_q[(long)((kc_) * 32 + kk_q) * HB + c_q]);         \
        }                                                                    \
        asm volatile("cp.async.commit_group;" ::: "memory");                 \
    }

    QKV_ISSUE(0, 0);
    QKV_ISSUE(1, 1);

    const int r0 = 16 * wr + g;

    for (int ck = 0; ck < 32; ck++) {
        if (ck < 31)
            asm volatile("cp.async.wait_group 1;" ::: "memory");
        else
            asm volatile("cp.async.wait_group 0;" ::: "memory");
        __syncthreads();   // stage ck%2 holds chunk ck, visible to all

        const float* xb = qsm + (ck & 1) * QKV_STG;
        const float* wb = xb + 64 * XS_STR;

#pragma unroll
        for (int kk8 = 0; kk8 < 4; kk8++) {
            uint32_t a[4];
            a[0] = f2tf(xb[r0 * XS_STR + 8 * kk8 + tig]);
            a[1] = f2tf(xb[(r0 + 8) * XS_STR + 8 * kk8 + tig]);
            a[2] = f2tf(xb[r0 * XS_STR + 8 * kk8 + tig + 4]);
            a[3] = f2tf(xb[(r0 + 8) * XS_STR + 8 * kk8 + tig + 4]);
            const float* w0 = wb + (8 * kk8 + tig) * WS_STR + 96 * wc;
            const float* w1 = wb + (8 * kk8 + tig + 4) * WS_STR + 96 * wc;
#pragma unroll
            for (int nt = 0; nt < 12; nt++)
                mma8(acc[nt], a, f2tf(w0[8 * nt + g]), f2tf(w1[8 * nt + g]));
        }

        __syncthreads();   // all warps done reading stage ck%2
        if (ck + 2 < 32) QKV_ISSUE(ck + 2, ck & 1);
    }

    // epilogue: add bias, scatter to g_k / g_q / g_v
#pragma unroll
    for (int nt = 0; nt < 12; nt++) {
        int gcol = 96 * wc + 8 * nt + 2 * tig;
        int m = gcol >> 6, lc = gcol & 63;
        const float* bp = (m == 0) ? bk : ((m == 1) ? bq : bv);
        float* op = (m == 0) ? g_k : ((m == 1) ? g_q : g_v);
        float b0 = bp[lc], b1 = bp[lc + 1];
        float* o = op + (row0 + r0) * HB + lc;
        *(float2*)o = make_float2(acc[nt][0] + b0, acc[nt][1] + b1);
        *(float2*)(o + 8 * HB) = make_float2(acc[nt][2] + b0, acc[nt][3] + b1);
    }
}

// ---------------------------------------------------------------------------
// Kernel 2: causal flash attention, tf32 mma, 128-row Q tiles, full-width
// warps (8 warps x 16 rows x 64 keys), split-K z=4. (R12 version, the
// 146.2us champion; R13's perm16 vectorization was neutral and reverted.)
// Grid (16, 4, 4); fixed-shift softmax; cp.async ping-pong K/V; P staging
// warp-private (syncwarp only). 2 blocks/SM.
// ---------------------------------------------------------------------------
#define KS_STR 68
#define VS_STR 72
#define PS_STR 68
#define KS0_OFF 0
#define KS1_OFF (64 * KS_STR)
#define VS0_OFF (2 * 64 * KS_STR)
#define VS1_OFF (VS0_OFF + 64 * VS_STR)
#define PS_OFF  (VS0_OFF + 2 * 64 * VS_STR)
#define ATTN_SMEM ((PS_OFF + 128 * PS_STR) * 4)   // 106496 B

__global__ __launch_bounds__(256, 2) void attn_kernel()
{
    extern __shared__ uint32_t sm[];
    uint32_t* ps = sm + PS_OFF;            // [128 rows][key] tf32, warp-private rows

    const int tid  = threadIdx.x;
    const int lane = tid & 31;
    const int wid  = tid >> 5;             // 0..7 = row group
    const int g    = lane >> 2;            // 0..7
    const int tig  = lane & 3;             // 0..3

    const int b = blockIdx.y;
    const int p = blockIdx.x;              // 0..15
    const int z = blockIdx.z;              // 0..3
    const long base = (long)b * TB * HB;
    const float QSC = 0.125f * 1.44269504088896f;  // scale * log2(e)

    const int lr0 = 16 * wid + g;          // local row in 0..127
    const int lr1 = lr0 + 8;

    const uint32_t ksu[2] = { (uint32_t)__cvta_generic_to_shared(sm + KS0_OFF),
                              (uint32_t)__cvta_generic_to_shared(sm + KS1_OFF) };
    const uint32_t vsu[2] = { (uint32_t)__cvta_generic_to_shared(sm + VS0_OFF),
                              (uint32_t)__cvta_generic_to_shared(sm + VS1_OFF) };

#define ATTN_ISSUE(jt_, bi_)                                                 \
    {                                                                        \
        const float* kp_a = g_k + base + (long)((jt_) * 64) * HB;            \
        const float* vp_a = g_v + base + (long)((jt_) * 64) * HB;            \
        _Pragma("unroll")                                                    \
        for (int i_a = 0; i_a < 4; i_a++) {                                  \
            int f_a = tid + 256 * i_a;                                       \
            int r_a = f_a >> 4, c_a = (f_a & 15) * 4;                        \
            CP_ASYNC16(ksu[bi_] + (r_a * KS_STR + c_a) * 4,                  \
                       kp_a + r_a * HB + c_a);                               \
            CP_ASYNC16(vsu[bi_] + (r_a * VS_STR + c_a) * 4,                  \
                       vp_a + r_a * HB + c_a);                               \
        }                                                                    \
        asm volatile("cp.async.commit_group;" ::: "memory");                 \
    }

#pragma unroll 1
    for (int half = 0; half < 2; half++) {
        const int t  = half ? (31 - p) : p;   // 128-row Q tile index
        const int n  = 2 * t + 2;             // total 64-key tiles for tile t
        const int j0 = (z * n) >> 2;
        const int j1 = (((z + 1) * n) >> 2) - 1;
        const int cnt = j1 - j0 + 1;          // may be 0

        // ---- Q fragments (16 rows per warp), pre-scaled by scale*log2e ----
        uint32_t aq[8][4];
        {
            const float* qp = g_q + base + (long)t * 128 * HB;
#pragma unroll
            for (int k = 0; k < 8; k++) {
                int c0 = k * 8 + tig;
                aq[k][0] = f2tf(qp[lr0 * HB + c0] * QSC);
                aq[k][1] = f2tf(qp[lr1 * HB + c0] * QSC);
                aq[k][2] = f2tf(qp[lr0 * HB + c0 + 4] * QSC);
                aq[k][3] = f2tf(qp[lr1 * HB + c0 + 4] * QSC);
            }
        }

        float l0 = 0.f, l1 = 0.f;
        float acc[8][4];
#pragma unroll
        for (int nt = 0; nt < 8; nt++)
#pragma unroll
            for (int c = 0; c < 4; c++) acc[nt][c] = 0.f;

        if (cnt >= 1) ATTN_ISSUE(j0, 0);
        if (cnt >= 2) ATTN_ISSUE(j0 + 1, 1);

        for (int jt = j0; jt <= j1; jt++) {
            const int cur = (jt - j0) & 1;
            if (jt < j1)
                asm volatile("cp.async.wait_group 1;" ::: "memory");
            else
                asm volatile("cp.async.wait_group 0;" ::: "memory");
            __syncthreads();   // tile jt visible to all threads

            const uint32_t* ksb = sm + (cur ? KS1_OFF : KS0_OFF);
            const uint32_t* vsb = sm + (cur ? VS1_OFF : VS0_OFF);
            const int koff = 64 * jt - 128 * t;   // for causal mask
            const bool diag = (jt >= 2 * t);

            // ---- S' = (Q*QSC) K^T in two nt-halves (keeps regs low),
            //      then softmax + warp-private P staging ----
#pragma unroll 1
            for (int pass = 0; pass < 2; pass++) {
                float sfr[4][4];
#pragma unroll
                for (int nt = 0; nt < 4; nt++)
#pragma unroll
                    for (int c = 0; c < 4; c++) sfr[nt][c] = 0.f;

#pragma unroll
                for (int nt = 0; nt < 4; nt++) {
                    int ntg = pass * 4 + nt;
                    const uint32_t* krow = &ksb[(8 * ntg + g) * KS_STR];
#pragma unroll
                    for (int k = 0; k < 8; k++) {
                        uint32_t b0 = krow[8 * k + tig];
                        uint32_t b1 = krow[8 * k + tig + 4];
                        mma8(sfr[nt], aq[k], b0, b1);
                    }
                }

                if (diag) {
#pragma unroll
                    for (int nt = 0; nt < 4; nt++) {
                        int c0 = 8 * (pass * 4 + nt) + 2 * tig;
#pragma unroll
                        for (int c = 0; c < 4; c++) {
                            int lc = c0 + (c & 1);
                            int lr = (c < 2) ? lr0 : lr1;
                            if (lc + koff > lr) sfr[nt][c] = -1e30f;
                        }
                    }
                }

#pragma unroll
                for (int nt = 0; nt < 4; nt++) {
                    float e0 = exp2f(sfr[nt][0]);
                    float e1 = exp2f(sfr[nt][1]);
                    float e2 = exp2f(sfr[nt][2]);
                    float e3 = exp2f(sfr[nt][3]);
                    l0 += e0 + e1;
                    l1 += e2 + e3;
                    int col = 8 * (pass * 4 + nt) + 2 * tig;
                    *(uint2*)&ps[lr0 * PS_STR + col] =
                        make_uint2(f2tf(e0), f2tf(e1));
                    *(uint2*)&ps[lr1 * PS_STR + col] =
                        make_uint2(f2tf(e2), f2tf(e3));
                }
            }
            __syncwarp();   // P rows are warp-private: no block barrier

            // ---- O += P V : 16 rows x 64 cols per warp ----
#pragma unroll
            for (int kg = 0; kg < 8; kg++) {
                uint32_t ap[4];
                ap[0] = ps[lr0 * PS_STR + 8 * kg + tig];
                ap[1] = ps[lr1 * PS_STR + 8 * kg + tig];
                ap[2] = ps[lr0 * PS_STR + 8 * kg + tig + 4];
                ap[3] = ps[lr1 * PS_STR + 8 * kg + tig + 4];
                const uint32_t* v0 = &vsb[(8 * kg + tig) * VS_STR];
                const uint32_t* v1 = &vsb[(8 * kg + tig + 4) * VS_STR];
#pragma unroll
                for (int nt = 0; nt < 8; nt++)
                    mma8(acc[nt], ap, v0[8 * nt + g], v1[8 * nt + g]);
            }

            __syncthreads();   // all warps done with buf[cur]
            if (jt + 2 <= j1) ATTN_ISSUE(jt + 2, cur);
        }

        // ---- in-warp row-sum reduce; write partials ----
        l0 += __shfl_xor_sync(0xffffffffu, l0, 1);
        l0 += __shfl_xor_sync(0xffffffffu, l0, 2);
        l1 += __shfl_xor_sync(0xffffffffu, l1, 1);
        l1 += __shfl_xor_sync(0xffffffffu, l1, 2);

        const long pidx = (long)((b * 32 + t) * 4 + z);
        if (tig == 0) {
            g_pl[pidx * 128 + lr0] = l0;
            g_pl[pidx * 128 + lr1] = l1;
        }
        float* pa = g_pacc + pidx * 128 * 64;
#pragma unroll
        for (int nt = 0; nt < 8; nt++) {
            int col = 8 * nt + 2 * tig;
            *(float2*)&pa[lr0 * 64 + col] = make_float2(acc[nt][0], acc[nt][1]);
            *(float2*)&pa[lr1 * 64 + col] = make_float2(acc[nt][2], acc[nt][3]);
        }
    }
}

// ---------------------------------------------------------------------------
// Kernel 3: combine 4 split-K partials. Grid (32, 4, 2): one block per
// (row tile t, batch, 64-row half). out = (sum_z acc) / (sum_z l).
// ---------------------------------------------------------------------------
__global__ __launch_bounds__(256) void combine_kernel(float* __restrict__ out)
{
    const int t = blockIdx.x, b = blockIdx.y, hf = blockIdx.z;
    const int tid = threadIdx.x;
    const int rbase = hf * 64;
    const long pbase = (long)((b * 32 + t) * 4);

    __shared__ float linv[64];
    if (tid < 64) {
        float s = 0.f;
#pragma unroll
        for (int z = 0; z < 4; z++)
            s += g_pl[(pbase + z) * 128 + rbase + tid];
        linv[tid] = 1.f / s;
    }
    __syncthreads();

    float* op = out + ((long)b * TB + (long)t * 128 + rbase) * HB;
#pragma unroll
    for (int i = 0; i < 4; i++) {
        int f = tid + 256 * i;
        int r = f >> 4, c = (f & 15) * 4;
        float4 a = make_float4(0.f, 0.f, 0.f, 0.f);
#pragma unroll
        for (int z = 0; z < 4; z++) {
            const float* pa = g_pacc + (pbase + z) * 128 * 64;
            float4 v = *(const float4*)&pa[(rbase + r) * 64 + c];
            a.x += v.x; a.y += v.y; a.z += v.z; a.w += v.w;
        }
        float s = linv[r];
        *(float4*)&op[r * HB + c] =
            make_float4(a.x * s, a.y * s, a.z * s, a.w * s);
    }
}

extern "C" void kernel_launch(void* const* d_in, const int* in_sizes, int n_in,
                              void* d_out, int out_size)
{
    const float* x  = (const float*)d_in[0];
    const float* Wk = (const float*)d_in[1];
    const float* bk = (const float*)d_in[2];
    const float* Wq = (const float*)d_in[3];
    const float* bq = (const float*)d_in[4];
    const float* Wv = (const float*)d_in[5];
    const float* bv = (const float*)d_in[6];
    float* out = (float*)d_out;

    (void)in_sizes; (void)n_in; (void)out_size;

    static bool attr_done = false;
    if (!attr_done) {
        cudaFuncSetAttribute(attn_kernel,
                             cudaFuncAttributeMaxDynamicSharedMemorySize,
                             ATTN_SMEM);
        cudaFuncSetAttribute(qkv_kernel,
                             cudaFuncAttributeMaxDynamicSharedMemorySize,
                             QKV_SMEM);
        attr_done = true;
    }

    qkv_kernel<<<256, 256, QKV_SMEM>>>(x, Wk, bk, Wq, bq, Wv, bv);
    attn_kernel<<<dim3(16, 4, 4), 256, ATTN_SMEM>>>();
    combine_kernel<<<dim3(32, 4, 2), 256>>>(out);
}